// round 5
// baseline (speedup 1.0000x reference)
#include <cuda_runtime.h>
#include <cuda_bf16.h>

#define NN 50000
#define NR 16
#define NE 800000
#define NH 64
#define NC 16

typedef unsigned long long ull;

// f32x2 packed-FMA helpers (Blackwell FFMA2 path, PTX-only)
__device__ __forceinline__ ull pk2(float lo, float hi) {
    ull r; asm("mov.b64 %0, {%1, %2};" : "=l"(r) : "f"(lo), "f"(hi)); return r;
}
__device__ __forceinline__ void fma2(ull& d, ull a, ull b) {
    asm("fma.rn.f32x2 %0, %1, %2, %0;" : "+l"(d) : "l"(a), "l"(b));
}
__device__ __forceinline__ float2 upk2(ull v) {
    float2 f; asm("mov.b64 {%0, %1}, %2;" : "=f"(f.x), "=f"(f.y) : "l"(v)); return f;
}

// Scratch (no allocations allowed -> __device__ globals)
__device__ float gH1[(size_t)NR * NN * NH];   // 204.8 MB
__device__ float gX1[(size_t)NN * NH];        // 12.8 MB
__device__ float gH2[(size_t)NR * NN * NC];   // 51.2 MB
__device__ int   gCnt[NN * NR];               // 3.2 MB

__global__ void zero_cnt_kernel() {
    int i = blockIdx.x * blockDim.x + threadIdx.x;
    if (i < NN * NR) gCnt[i] = 0;
}

__global__ void count_kernel(const int* __restrict__ dst, const int* __restrict__ et) {
    int e = blockIdx.x * blockDim.x + threadIdx.x;
    if (e < NE) atomicAdd(&gCnt[dst[e] * NR + et[e]], 1);
}

// H1[r] = X @ W1[r] (r<16); r==16: X1 = X @ root1 + b1
// 64x64 tile, 256 threads, each thread 2 rows x 8 cols via f32x2 FMA.
__global__ __launch_bounds__(256) void transform1_kernel(
    const float* __restrict__ x, const float* __restrict__ W1,
    const float* __restrict__ root1, const float* __restrict__ b1) {
    __shared__ float sX[64][65];
    __shared__ float sW[64][64];
    int r  = blockIdx.y;
    int n0 = blockIdx.x * 64;
    const float* Wp = (r < NR) ? (W1 + (size_t)r * NH * NH) : root1;

    for (int i = threadIdx.x; i < NH * NH; i += 256) {
        int row = i >> 6, col = i & 63;
        sW[row][col] = Wp[i];
        int n = n0 + row;
        sX[row][col] = (n < NN) ? x[(size_t)n * NH + col] : 0.f;
    }
    __syncthreads();

    int tx = threadIdx.x & 7;    // c0 = tx*8
    int ty = threadIdx.x >> 3;   // r0 = ty*2
    int c0 = tx * 8, r0 = ty * 2;

    ull acc[2][4];
#pragma unroll
    for (int i = 0; i < 2; i++)
#pragma unroll
        for (int j = 0; j < 4; j++) acc[i][j] = 0ull;

#pragma unroll 8
    for (int k = 0; k < 64; k++) {
        // adjacent float pairs ARE f32x2 operands -> no pack instructions for W
        ulonglong2 wab = *(const ulonglong2*)&sW[k][c0];
        ulonglong2 wcd = *(const ulonglong2*)&sW[k][c0 + 4];
        float xa = sX[r0][k];
        float xb = sX[r0 + 1][k];
        ull xaa = pk2(xa, xa);
        ull xbb = pk2(xb, xb);
        fma2(acc[0][0], xaa, wab.x); fma2(acc[0][1], xaa, wab.y);
        fma2(acc[0][2], xaa, wcd.x); fma2(acc[0][3], xaa, wcd.y);
        fma2(acc[1][0], xbb, wab.x); fma2(acc[1][1], xbb, wab.y);
        fma2(acc[1][2], xbb, wcd.x); fma2(acc[1][3], xbb, wcd.y);
    }

#pragma unroll
    for (int i = 0; i < 2; i++) {
        int n = n0 + r0 + i;
        if (n >= NN) continue;
        float2 p0 = upk2(acc[i][0]), p1 = upk2(acc[i][1]);
        float2 p2 = upk2(acc[i][2]), p3 = upk2(acc[i][3]);
        if (r < NR) {
            float4* o = (float4*)(gH1 + ((size_t)r * NN + n) * NH + c0);
            __stcs(o,     make_float4(p0.x, p0.y, p1.x, p1.y));
            __stcs(o + 1, make_float4(p2.x, p2.y, p3.x, p3.y));
        } else {
            const float4 ba = *(const float4*)&b1[c0];
            const float4 bb = *(const float4*)&b1[c0 + 4];
            float4* o = (float4*)(gX1 + (size_t)n * NH + c0);
            o[0] = make_float4(p0.x + ba.x, p0.y + ba.y, p1.x + ba.z, p1.y + ba.w);
            o[1] = make_float4(p2.x + bb.x, p2.y + bb.y, p3.x + bb.z, p3.y + bb.w);
        }
    }
}

// Per edge: X1[dst] += H1[et][src] / cnt[dst][et].
// 16 lanes per edge-PAIR slot: each thread serves edges g and g+NE/2 (MLP=2).
__global__ __launch_bounds__(256) void scatter1_kernel(
    const int* __restrict__ src, const int* __restrict__ dst, const int* __restrict__ et) {
    int t = blockIdx.x * 256 + threadIdx.x;
    int g = t >> 4;
    if (g >= NE / 2) return;
    int lane = t & 15;
    int eA = g, eB = g + NE / 2;
    // warp-uniform index loads (hardware broadcast within warp)
    int sA = __ldg(src + eA), dA = __ldg(dst + eA), rA = __ldg(et + eA);
    int sB = __ldg(src + eB), dB = __ldg(dst + eB), rB = __ldg(et + eB);
    float4 vA = __ldcs(((const float4*)(gH1 + ((size_t)rA * NN + sA) * NH)) + lane);
    float4 vB = __ldcs(((const float4*)(gH1 + ((size_t)rB * NN + sB) * NH)) + lane);
    float wA = 1.0f / (float)gCnt[dA * NR + rA];
    float wB = 1.0f / (float)gCnt[dB * NR + rB];
    vA.x *= wA; vA.y *= wA; vA.z *= wA; vA.w *= wA;
    vB.x *= wB; vB.y *= wB; vB.z *= wB; vB.w *= wB;
    atomicAdd(((float4*)(gX1 + (size_t)dA * NH)) + lane, vA);
    atomicAdd(((float4*)(gX1 + (size_t)dB * NH)) + lane, vB);
}

// H2[r] = relu(X1) @ W2[r]; r==16: out = relu(X1) @ root2 + b2
// 128-node x 16-col tile, 256 threads, each thread 1 row x 8 cols via f32x2.
__global__ __launch_bounds__(256) void transform2_kernel(
    const float* __restrict__ W2, const float* __restrict__ root2,
    const float* __restrict__ b2, float* __restrict__ out) {
    __shared__ float sX[128][65];
    __shared__ float sW[64][16];
    int r  = blockIdx.y;
    int n0 = blockIdx.x * 128;
    const float* Wp = (r < NR) ? (W2 + (size_t)r * NH * NC) : root2;

    for (int i = threadIdx.x; i < NH * NC; i += 256)
        sW[i >> 4][i & 15] = Wp[i];
    for (int i = threadIdx.x; i < 128 * NH; i += 256) {
        int row = i >> 6, col = i & 63;
        int n = n0 + row;
        float v = (n < NN) ? gX1[(size_t)n * NH + col] : 0.f;
        sX[row][col] = fmaxf(v, 0.f);   // fused ReLU
    }
    __syncthreads();

    int tx = threadIdx.x & 1;    // c0 = tx*8
    int ty = threadIdx.x >> 1;   // row = ty (0..127)
    int c0 = tx * 8;

    ull acc[4];
#pragma unroll
    for (int j = 0; j < 4; j++) acc[j] = 0ull;

#pragma unroll 8
    for (int k = 0; k < 64; k++) {
        ulonglong2 wab = *(const ulonglong2*)&sW[k][c0];
        ulonglong2 wcd = *(const ulonglong2*)&sW[k][c0 + 4];
        float xa = sX[ty][k];
        ull xaa = pk2(xa, xa);
        fma2(acc[0], xaa, wab.x); fma2(acc[1], xaa, wab.y);
        fma2(acc[2], xaa, wcd.x); fma2(acc[3], xaa, wcd.y);
    }

    int n = n0 + ty;
    if (n >= NN) return;
    float2 p0 = upk2(acc[0]), p1 = upk2(acc[1]);
    float2 p2 = upk2(acc[2]), p3 = upk2(acc[3]);
    if (r < NR) {
        float4* o = (float4*)(gH2 + ((size_t)r * NN + n) * NC + c0);
        __stcs(o,     make_float4(p0.x, p0.y, p1.x, p1.y));
        __stcs(o + 1, make_float4(p2.x, p2.y, p3.x, p3.y));
    } else {
        const float4 ba = *(const float4*)&b2[c0];
        const float4 bb = *(const float4*)&b2[c0 + 4];
        float4* o = (float4*)(out + (size_t)n * NC + c0);
        o[0] = make_float4(p0.x + ba.x, p0.y + ba.y, p1.x + ba.z, p1.y + ba.w);
        o[1] = make_float4(p2.x + bb.x, p2.y + bb.y, p3.x + bb.z, p3.y + bb.w);
    }
}

// Per edge: out[dst] += H2[et][src] / cnt[dst][et]. 4 lanes per edge-pair slot (MLP=2).
__global__ __launch_bounds__(256) void scatter2_kernel(
    const int* __restrict__ src, const int* __restrict__ dst, const int* __restrict__ et,
    float* __restrict__ out) {
    int t = blockIdx.x * 256 + threadIdx.x;
    int g = t >> 2;
    if (g >= NE / 2) return;
    int lane = t & 3;
    int eA = g, eB = g + NE / 2;
    int sA = __ldg(src + eA), dA = __ldg(dst + eA), rA = __ldg(et + eA);
    int sB = __ldg(src + eB), dB = __ldg(dst + eB), rB = __ldg(et + eB);
    float4 vA = __ldcs(((const float4*)(gH2 + ((size_t)rA * NN + sA) * NC)) + lane);
    float4 vB = __ldcs(((const float4*)(gH2 + ((size_t)rB * NN + sB) * NC)) + lane);
    float wA = 1.0f / (float)gCnt[dA * NR + rA];
    float wB = 1.0f / (float)gCnt[dB * NR + rB];
    vA.x *= wA; vA.y *= wA; vA.z *= wA; vA.w *= wA;
    vB.x *= wB; vB.y *= wB; vB.z *= wB; vB.w *= wB;
    atomicAdd(((float4*)(out + (size_t)dA * NC)) + lane, vA);
    atomicAdd(((float4*)(out + (size_t)dB * NC)) + lane, vB);
}

extern "C" void kernel_launch(void* const* d_in, const int* in_sizes, int n_in,
                              void* d_out, int out_size) {
    const int*   edge_index = (const int*)d_in[0];   // [2, NE]
    const int*   edge_type  = (const int*)d_in[1];   // [NE]
    const float* node_emb   = (const float*)d_in[2]; // [NN, NH]
    const float* W1         = (const float*)d_in[3]; // [NR, NH, NH]
    const float* root1      = (const float*)d_in[4]; // [NH, NH]
    const float* b1         = (const float*)d_in[5]; // [NH]
    const float* W2         = (const float*)d_in[6]; // [NR, NH, NC]
    const float* root2      = (const float*)d_in[7]; // [NH, NC]
    const float* b2         = (const float*)d_in[8]; // [NC]
    float* out = (float*)d_out;                      // [NN, NC]

    const int* src = edge_index;
    const int* dst = edge_index + NE;

    zero_cnt_kernel<<<(NN * NR + 255) / 256, 256>>>();
    count_kernel<<<(NE + 255) / 256, 256>>>(dst, edge_type);

    dim3 tgrid1((NN + 63) / 64, NR + 1);
    transform1_kernel<<<tgrid1, 256>>>(node_emb, W1, root1, b1);
    scatter1_kernel<<<((NE / 2) * 16 + 255) / 256, 256>>>(src, dst, edge_type);
    dim3 tgrid2((NN + 127) / 128, NR + 1);
    transform2_kernel<<<tgrid2, 256>>>(W2, root2, b2, out);
    scatter2_kernel<<<((NE / 2) * 4 + 255) / 256, 256>>>(src, dst, edge_type, out);
}

// round 12
// speedup vs baseline: 1.2526x; 1.2526x over previous
#include <cuda_runtime.h>
#include <cuda_bf16.h>

#define NN 50000
#define NR 16
#define NE 800000
#define NH 64
#define NC 16

// Scratch (no allocations allowed -> __device__ globals)
__device__ float gH1[(size_t)NR * NN * NH];   // 204.8 MB
__device__ float gX1[(size_t)NN * NH];        // 12.8 MB
__device__ float gH2[(size_t)NR * NN * NC];   // 51.2 MB
__device__ int   gCnt[NN * NR];               // 3.2 MB

__global__ void zero_cnt_kernel() {
    int i = blockIdx.x * blockDim.x + threadIdx.x;
    if (i < NN * NR) gCnt[i] = 0;
}

__global__ void count_kernel(const int* __restrict__ dst, const int* __restrict__ et) {
    int e = blockIdx.x * blockDim.x + threadIdx.x;
    if (e < NE) atomicAdd(&gCnt[dst[e] * NR + et[e]], 1);
}

// No-op: shifts ncu's skip-based capture window so transform1 lands on the
// captured slot (previous rounds only ever profiled scatter1).
__global__ void profile_align_kernel() {}

// H1[r] = X @ W1[r]  (r<16); r==16: X1 = X @ root1 + b1
// Block: 64 nodes x 64 outputs. 256 threads, each computes 16 outputs. (round-4 verified)
__global__ __launch_bounds__(256) void transform1_kernel(
    const float* __restrict__ x, const float* __restrict__ W1,
    const float* __restrict__ root1, const float* __restrict__ b1) {
    __shared__ float sX[64][65];
    __shared__ float sW[64][64];
    int r  = blockIdx.y;
    int n0 = blockIdx.x * 64;
    const float* Wp = (r < NR) ? (W1 + (size_t)r * NH * NH) : root1;

    for (int i = threadIdx.x; i < NH * NH; i += 256) {
        int row = i >> 6, col = i & 63;
        sW[row][col] = Wp[i];
        int n = n0 + row;
        sX[row][col] = (n < NN) ? x[(size_t)n * NH + col] : 0.f;
    }
    __syncthreads();

    int row  = threadIdx.x & 63;
    int quad = threadIdx.x >> 6;   // 0..3 -> output columns [quad*16, quad*16+16)
    float acc[16];
#pragma unroll
    for (int j = 0; j < 16; j++) acc[j] = 0.f;

#pragma unroll
    for (int k = 0; k < 64; k++) {
        float xv = sX[row][k];
        const float4* wrow = (const float4*)&sW[k][quad * 16];
#pragma unroll
        for (int j4 = 0; j4 < 4; j4++) {
            float4 w = wrow[j4];
            acc[j4 * 4 + 0] += xv * w.x;
            acc[j4 * 4 + 1] += xv * w.y;
            acc[j4 * 4 + 2] += xv * w.z;
            acc[j4 * 4 + 3] += xv * w.w;
        }
    }

    int n = n0 + row;
    if (n >= NN) return;
    if (r < NR) {
        float4* o = (float4*)(gH1 + ((size_t)r * NN + n) * NH + quad * 16);
#pragma unroll
        for (int j4 = 0; j4 < 4; j4++)
            __stcs(o + j4, make_float4(acc[j4*4+0], acc[j4*4+1], acc[j4*4+2], acc[j4*4+3]));
    } else {
        float* o = gX1 + (size_t)n * NH + quad * 16;
#pragma unroll
        for (int j = 0; j < 16; j++) o[j] = acc[j] + b1[quad * 16 + j];
    }
}

// Per edge: X1[dst] += H1[et][src] / cnt[dst][et].
// 16 lanes per edge-PAIR slot: each thread serves edges g and g+NE/2 (MLP=2). (round-5 verified)
__global__ __launch_bounds__(256) void scatter1_kernel(
    const int* __restrict__ src, const int* __restrict__ dst, const int* __restrict__ et) {
    int t = blockIdx.x * 256 + threadIdx.x;
    int g = t >> 4;
    if (g >= NE / 2) return;
    int lane = t & 15;
    int eA = g, eB = g + NE / 2;
    // warp-uniform index loads (hardware broadcast within warp)
    int sA = __ldg(src + eA), dA = __ldg(dst + eA), rA = __ldg(et + eA);
    int sB = __ldg(src + eB), dB = __ldg(dst + eB), rB = __ldg(et + eB);
    float4 vA = __ldcs(((const float4*)(gH1 + ((size_t)rA * NN + sA) * NH)) + lane);
    float4 vB = __ldcs(((const float4*)(gH1 + ((size_t)rB * NN + sB) * NH)) + lane);
    float wA = 1.0f / (float)gCnt[dA * NR + rA];
    float wB = 1.0f / (float)gCnt[dB * NR + rB];
    vA.x *= wA; vA.y *= wA; vA.z *= wA; vA.w *= wA;
    vB.x *= wB; vB.y *= wB; vB.z *= wB; vB.w *= wB;
    atomicAdd(((float4*)(gX1 + (size_t)dA * NH)) + lane, vA);
    atomicAdd(((float4*)(gX1 + (size_t)dB * NH)) + lane, vB);
}

// H2[r] = relu(X1) @ W2[r]; r==16: out = relu(X1) @ root2 + b2
// Block: 64 nodes x 16 outputs. 256 threads, each computes 4 outputs. (round-4 verified)
__global__ __launch_bounds__(256) void transform2_kernel(
    const float* __restrict__ W2, const float* __restrict__ root2,
    const float* __restrict__ b2, float* __restrict__ out) {
    __shared__ float sX[64][65];
    __shared__ float sW[64][16];
    int r  = blockIdx.y;
    int n0 = blockIdx.x * 64;
    const float* Wp = (r < NR) ? (W2 + (size_t)r * NH * NC) : root2;

    for (int i = threadIdx.x; i < NH * NC; i += 256)
        sW[i >> 4][i & 15] = Wp[i];
    for (int i = threadIdx.x; i < 64 * 64; i += 256) {
        int row = i >> 6, col = i & 63;
        int n = n0 + row;
        float v = (n < NN) ? gX1[(size_t)n * NH + col] : 0.f;
        sX[row][col] = fmaxf(v, 0.f);   // fused ReLU
    }
    __syncthreads();

    int row  = threadIdx.x & 63;
    int part = threadIdx.x >> 6;   // 0..3 -> output columns [part*4, part*4+4)
    float a0 = 0.f, a1 = 0.f, a2 = 0.f, a3 = 0.f;
#pragma unroll
    for (int k = 0; k < 64; k++) {
        float xv = sX[row][k];
        float4 w = *(const float4*)&sW[k][part * 4];
        a0 += xv * w.x; a1 += xv * w.y; a2 += xv * w.z; a3 += xv * w.w;
    }

    int n = n0 + row;
    if (n >= NN) return;
    if (r < NR) {
        __stcs((float4*)(gH2 + ((size_t)r * NN + n) * NC + part * 4),
               make_float4(a0, a1, a2, a3));
    } else {
        const float4 b = *(const float4*)(b2 + part * 4);
        *(float4*)(out + (size_t)n * NC + part * 4) =
            make_float4(a0 + b.x, a1 + b.y, a2 + b.z, a3 + b.w);
    }
}

// Per edge: out[dst] += H2[et][src] / cnt[dst][et]. 4 lanes per edge-pair slot (MLP=2). (round-5)
__global__ __launch_bounds__(256) void scatter2_kernel(
    const int* __restrict__ src, const int* __restrict__ dst, const int* __restrict__ et,
    float* __restrict__ out) {
    int t = blockIdx.x * 256 + threadIdx.x;
    int g = t >> 2;
    if (g >= NE / 2) return;
    int lane = t & 3;
    int eA = g, eB = g + NE / 2;
    int sA = __ldg(src + eA), dA = __ldg(dst + eA), rA = __ldg(et + eA);
    int sB = __ldg(src + eB), dB = __ldg(dst + eB), rB = __ldg(et + eB);
    float4 vA = __ldcs(((const float4*)(gH2 + ((size_t)rA * NN + sA) * NC)) + lane);
    float4 vB = __ldcs(((const float4*)(gH2 + ((size_t)rB * NN + sB) * NC)) + lane);
    float wA = 1.0f / (float)gCnt[dA * NR + rA];
    float wB = 1.0f / (float)gCnt[dB * NR + rB];
    vA.x *= wA; vA.y *= wA; vA.z *= wA; vA.w *= wA;
    vB.x *= wB; vB.y *= wB; vB.z *= wB; vB.w *= wB;
    atomicAdd(((float4*)(out + (size_t)dA * NC)) + lane, vA);
    atomicAdd(((float4*)(out + (size_t)dB * NC)) + lane, vB);
}

extern "C" void kernel_launch(void* const* d_in, const int* in_sizes, int n_in,
                              void* d_out, int out_size) {
    const int*   edge_index = (const int*)d_in[0];   // [2, NE]
    const int*   edge_type  = (const int*)d_in[1];   // [NE]
    const float* node_emb   = (const float*)d_in[2]; // [NN, NH]
    const float* W1         = (const float*)d_in[3]; // [NR, NH, NH]
    const float* root1      = (const float*)d_in[4]; // [NH, NH]
    const float* b1         = (const float*)d_in[5]; // [NH]
    const float* W2         = (const float*)d_in[6]; // [NR, NH, NC]
    const float* root2      = (const float*)d_in[7]; // [NH, NC]
    const float* b2         = (const float*)d_in[8]; // [NC]
    float* out = (float*)d_out;                      // [NN, NC]

    const int* src = edge_index;
    const int* dst = edge_index + NE;

    zero_cnt_kernel<<<(NN * NR + 255) / 256, 256>>>();
    count_kernel<<<(NE + 255) / 256, 256>>>(dst, edge_type);
    profile_align_kernel<<<1, 32>>>();   // shift ncu capture slot onto transform1

    dim3 tgrid((NN + 63) / 64, NR + 1);
    transform1_kernel<<<tgrid, 256>>>(node_emb, W1, root1, b1);
    scatter1_kernel<<<((NE / 2) * 16 + 255) / 256, 256>>>(src, dst, edge_type);
    transform2_kernel<<<tgrid, 256>>>(W2, root2, b2, out);
    scatter2_kernel<<<((NE / 2) * 4 + 255) / 256, 256>>>(src, dst, edge_type, out);
}

// round 14
// speedup vs baseline: 1.6770x; 1.3388x over previous
#include <cuda_runtime.h>
#include <cuda_bf16.h>

#define NN 50000
#define NR 16
#define NE 800000
#define NH 64
#define NC 16

// Scratch (no allocations allowed -> __device__ globals)
__device__ float gH1[(size_t)NR * NN * NH];   // 204.8 MB
__device__ float gX1[(size_t)NN * NH];        // 12.8 MB
__device__ float gH2[(size_t)NR * NN * NC];   // 51.2 MB
__device__ int   gCnt[NN * NR];               // 3.2 MB

__global__ void zero_cnt_kernel() {
    int i = blockIdx.x * blockDim.x + threadIdx.x;
    if (i < NN * NR) gCnt[i] = 0;
}

__global__ void count_kernel(const int* __restrict__ dst, const int* __restrict__ et) {
    int e = blockIdx.x * blockDim.x + threadIdx.x;
    if (e < NE) atomicAdd(&gCnt[dst[e] * NR + et[e]], 1);
}

// No-op: keeps ncu capture slot on transform1 (verified working in round 12).
__global__ void profile_align_kernel() {}

// H1[r] = X @ W1[r] (r<16); r==16: X1 = X @ root1 + b1
// Tile 128 nodes x 64 cols; 256 threads; thread = 4 rows x 8 cols (c0, c0+32).
// K processed in 2 chunks of 32 to fit smem (32.5 KB -> high occupancy).
// Per k: 4 scalar LDS (conflict-free) + 2 LDS.128 (conflict-free) per 32 FFMA.
__global__ __launch_bounds__(256) void transform1_kernel(
    const float* __restrict__ x, const float* __restrict__ W1,
    const float* __restrict__ root1, const float* __restrict__ b1) {
    __shared__ float sX[128][33];   // [row][k within chunk], stride 33: rows 4 apart -> banks 4 apart
    __shared__ float sW[64][64];
    int r  = blockIdx.y;
    int n0 = blockIdx.x * 128;
    const float* Wp = (r < NR) ? (W1 + (size_t)r * NH * NH) : root1;

    for (int i = threadIdx.x; i < NH * NH; i += 256)
        sW[i >> 6][i & 63] = Wp[i];

    int l = threadIdx.x & 31, w = threadIdx.x >> 5;
    int r0 = w * 16 + (l & 3) * 4;   // 4 rows: r0..r0+3 (warp covers 16 rows)
    int c0 = (l >> 2) * 4;           // cols c0..c0+3 and c0+32..c0+35

    float acc[4][8];
#pragma unroll
    for (int i = 0; i < 4; i++)
#pragma unroll
        for (int j = 0; j < 8; j++) acc[i][j] = 0.f;

    for (int kc = 0; kc < 2; kc++) {
        __syncthreads();   // also covers sW load on first iteration
        // load X chunk: 128 rows x 32 k-cols (coalesced 128B segments)
        for (int i = threadIdx.x; i < 128 * 32; i += 256) {
            int row = i >> 5, col = i & 31;
            int n = n0 + row;
            sX[row][col] = (n < NN) ? x[(size_t)n * NH + kc * 32 + col] : 0.f;
        }
        __syncthreads();
#pragma unroll 8
        for (int kk = 0; kk < 32; kk++) {
            int k = kc * 32 + kk;
            float4 wa = *(const float4*)&sW[k][c0];
            float4 wb = *(const float4*)&sW[k][c0 + 32];
            float xs0 = sX[r0 + 0][kk];
            float xs1 = sX[r0 + 1][kk];
            float xs2 = sX[r0 + 2][kk];
            float xs3 = sX[r0 + 3][kk];
#define T1ROW(i, xv) \
            acc[i][0] += xv * wa.x; acc[i][1] += xv * wa.y; \
            acc[i][2] += xv * wa.z; acc[i][3] += xv * wa.w; \
            acc[i][4] += xv * wb.x; acc[i][5] += xv * wb.y; \
            acc[i][6] += xv * wb.z; acc[i][7] += xv * wb.w;
            T1ROW(0, xs0) T1ROW(1, xs1) T1ROW(2, xs2) T1ROW(3, xs3)
#undef T1ROW
        }
    }

#pragma unroll
    for (int i = 0; i < 4; i++) {
        int n = n0 + r0 + i;
        if (n >= NN) continue;
        if (r < NR) {
            float* o = gH1 + ((size_t)r * NN + n) * NH;
            __stcs((float4*)(o + c0),
                   make_float4(acc[i][0], acc[i][1], acc[i][2], acc[i][3]));
            __stcs((float4*)(o + c0 + 32),
                   make_float4(acc[i][4], acc[i][5], acc[i][6], acc[i][7]));
        } else {
            const float4 ba = *(const float4*)&b1[c0];
            const float4 bb = *(const float4*)&b1[c0 + 32];
            float* o = gX1 + (size_t)n * NH;
            *(float4*)(o + c0) = make_float4(acc[i][0] + ba.x, acc[i][1] + ba.y,
                                             acc[i][2] + ba.z, acc[i][3] + ba.w);
            *(float4*)(o + c0 + 32) = make_float4(acc[i][4] + bb.x, acc[i][5] + bb.y,
                                                  acc[i][6] + bb.z, acc[i][7] + bb.w);
        }
    }
}

// Per edge: X1[dst] += H1[et][src] / cnt[dst][et].
// 16 lanes per edge-PAIR slot (MLP=2). (round-5 verified, unchanged)
__global__ __launch_bounds__(256) void scatter1_kernel(
    const int* __restrict__ src, const int* __restrict__ dst, const int* __restrict__ et) {
    int t = blockIdx.x * 256 + threadIdx.x;
    int g = t >> 4;
    if (g >= NE / 2) return;
    int lane = t & 15;
    int eA = g, eB = g + NE / 2;
    int sA = __ldg(src + eA), dA = __ldg(dst + eA), rA = __ldg(et + eA);
    int sB = __ldg(src + eB), dB = __ldg(dst + eB), rB = __ldg(et + eB);
    float4 vA = __ldcs(((const float4*)(gH1 + ((size_t)rA * NN + sA) * NH)) + lane);
    float4 vB = __ldcs(((const float4*)(gH1 + ((size_t)rB * NN + sB) * NH)) + lane);
    float wA = 1.0f / (float)gCnt[dA * NR + rA];
    float wB = 1.0f / (float)gCnt[dB * NR + rB];
    vA.x *= wA; vA.y *= wA; vA.z *= wA; vA.w *= wA;
    vB.x *= wB; vB.y *= wB; vB.z *= wB; vB.w *= wB;
    atomicAdd(((float4*)(gX1 + (size_t)dA * NH)) + lane, vA);
    atomicAdd(((float4*)(gX1 + (size_t)dB * NH)) + lane, vB);
}

// H2[r] = relu(X1) @ W2[r]; r==16: out = relu(X1) @ root2 + b2
// Tile 256 nodes x 16 cols; 256 threads; thread = 4 rows x 4 cols; k-chunked.
__global__ __launch_bounds__(256) void transform2_kernel(
    const float* __restrict__ W2, const float* __restrict__ root2,
    const float* __restrict__ b2, float* __restrict__ out) {
    __shared__ float sX[256][33];
    __shared__ float sW[64][16];
    int r  = blockIdx.y;
    int n0 = blockIdx.x * 256;
    const float* Wp = (r < NR) ? (W2 + (size_t)r * NH * NC) : root2;

    for (int i = threadIdx.x; i < NH * NC; i += 256)
        sW[i >> 4][i & 15] = Wp[i];

    int l = threadIdx.x & 31, w = threadIdx.x >> 5;
    int r0 = w * 32 + (l & 7) * 4;   // 4 rows (warp covers 32 rows)
    int c0 = (l >> 3) * 4;           // 4 cols

    float acc[4][4];
#pragma unroll
    for (int i = 0; i < 4; i++)
#pragma unroll
        for (int j = 0; j < 4; j++) acc[i][j] = 0.f;

    for (int kc = 0; kc < 2; kc++) {
        __syncthreads();
        for (int i = threadIdx.x; i < 256 * 32; i += 256) {
            int row = i >> 5, col = i & 31;
            int n = n0 + row;
            float v = (n < NN) ? gX1[(size_t)n * NH + kc * 32 + col] : 0.f;
            sX[row][col] = fmaxf(v, 0.f);   // fused ReLU
        }
        __syncthreads();
#pragma unroll 8
        for (int kk = 0; kk < 32; kk++) {
            int k = kc * 32 + kk;
            float4 wv = *(const float4*)&sW[k][c0];
            float xs0 = sX[r0 + 0][kk];
            float xs1 = sX[r0 + 1][kk];
            float xs2 = sX[r0 + 2][kk];
            float xs3 = sX[r0 + 3][kk];
#define T2ROW(i, xv) \
            acc[i][0] += xv * wv.x; acc[i][1] += xv * wv.y; \
            acc[i][2] += xv * wv.z; acc[i][3] += xv * wv.w;
            T2ROW(0, xs0) T2ROW(1, xs1) T2ROW(2, xs2) T2ROW(3, xs3)
#undef T2ROW
        }
    }

#pragma unroll
    for (int i = 0; i < 4; i++) {
        int n = n0 + r0 + i;
        if (n >= NN) continue;
        if (r < NR) {
            __stcs((float4*)(gH2 + ((size_t)r * NN + n) * NC + c0),
                   make_float4(acc[i][0], acc[i][1], acc[i][2], acc[i][3]));
        } else {
            const float4 b = *(const float4*)(b2 + c0);
            *(float4*)(out + (size_t)n * NC + c0) =
                make_float4(acc[i][0] + b.x, acc[i][1] + b.y,
                            acc[i][2] + b.z, acc[i][3] + b.w);
        }
    }
}

// Per edge: out[dst] += H2[et][src] / cnt[dst][et]. 4 lanes per edge-pair slot (MLP=2). (round-5)
__global__ __launch_bounds__(256) void scatter2_kernel(
    const int* __restrict__ src, const int* __restrict__ dst, const int* __restrict__ et,
    float* __restrict__ out) {
    int t = blockIdx.x * 256 + threadIdx.x;
    int g = t >> 2;
    if (g >= NE / 2) return;
    int lane = t & 3;
    int eA = g, eB = g + NE / 2;
    int sA = __ldg(src + eA), dA = __ldg(dst + eA), rA = __ldg(et + eA);
    int sB = __ldg(src + eB), dB = __ldg(dst + eB), rB = __ldg(et + eB);
    float4 vA = __ldcs(((const float4*)(gH2 + ((size_t)rA * NN + sA) * NC)) + lane);
    float4 vB = __ldcs(((const float4*)(gH2 + ((size_t)rB * NN + sB) * NC)) + lane);
    float wA = 1.0f / (float)gCnt[dA * NR + rA];
    float wB = 1.0f / (float)gCnt[dB * NR + rB];
    vA.x *= wA; vA.y *= wA; vA.z *= wA; vA.w *= wA;
    vB.x *= wB; vB.y *= wB; vB.z *= wB; vB.w *= wB;
    atomicAdd(((float4*)(out + (size_t)dA * NC)) + lane, vA);
    atomicAdd(((float4*)(out + (size_t)dB * NC)) + lane, vB);
}

extern "C" void kernel_launch(void* const* d_in, const int* in_sizes, int n_in,
                              void* d_out, int out_size) {
    const int*   edge_index = (const int*)d_in[0];   // [2, NE]
    const int*   edge_type  = (const int*)d_in[1];   // [NE]
    const float* node_emb   = (const float*)d_in[2]; // [NN, NH]
    const float* W1         = (const float*)d_in[3]; // [NR, NH, NH]
    const float* root1      = (const float*)d_in[4]; // [NH, NH]
    const float* b1         = (const float*)d_in[5]; // [NH]
    const float* W2         = (const float*)d_in[6]; // [NR, NH, NC]
    const float* root2      = (const float*)d_in[7]; // [NH, NC]
    const float* b2         = (const float*)d_in[8]; // [NC]
    float* out = (float*)d_out;                      // [NN, NC]

    const int* src = edge_index;
    const int* dst = edge_index + NE;

    zero_cnt_kernel<<<(NN * NR + 255) / 256, 256>>>();
    count_kernel<<<(NE + 255) / 256, 256>>>(dst, edge_type);
    profile_align_kernel<<<1, 32>>>();   // keep ncu capture slot on transform1

    dim3 tgrid1((NN + 127) / 128, NR + 1);
    transform1_kernel<<<tgrid1, 256>>>(node_emb, W1, root1, b1);
    scatter1_kernel<<<((NE / 2) * 16 + 255) / 256, 256>>>(src, dst, edge_type);
    dim3 tgrid2((NN + 255) / 256, NR + 1);
    transform2_kernel<<<tgrid2, 256>>>(W2, root2, b2, out);
    scatter2_kernel<<<((NE / 2) * 4 + 255) / 256, 256>>>(src, dst, edge_type, out);
}